// round 12
// baseline (speedup 1.0000x reference)
#include <cuda_runtime.h>
#include <cuda_bf16.h>

#define N_SEQ   256
#define M_GENES 2000
#define D_DIM   128
#define N_NUC   4
#define TABLE_ROWS (M_GENES * N_NUC)       // 8000
#define ROWS_PER_WARP 16
#define TOTAL_ROWS (N_SEQ * M_GENES)       // 512000

// Tiny scratch: one inverse norm per table row (32 KB)
__device__ float g_inv_norm[TABLE_ROWS];

// Kernel 1: inverse norms only. One warp per 128-float row; writes 1 float.
__global__ void norms_kernel(const float* __restrict__ emb) {
#if __CUDA_ARCH__ >= 900
    cudaTriggerProgrammaticLaunchCompletion();
#endif
    int warp = (blockIdx.x * blockDim.x + threadIdx.x) >> 5;
    int lane = threadIdx.x & 31;
    if (warp >= TABLE_ROWS) return;

    const float4* src = reinterpret_cast<const float4*>(emb + (size_t)warp * D_DIM);
    float4 v = __ldg(src + lane);
    float ss = v.x * v.x + v.y * v.y + v.z * v.z + v.w * v.w;
    #pragma unroll
    for (int o = 16; o > 0; o >>= 1)
        ss += __shfl_xor_sync(0xffffffffu, ss, o);

    if (lane == 0)
        g_inv_norm[warp] = 1.0f / fmaxf(sqrtf(ss), 1e-12f);
}

// Kernel 2: gather with TRUE MLP=16. 16 consecutive output rows per warp;
// all 16 row loads live in distinct registers and are issued before any
// consumption. 8 KB contiguous streaming write per warp.
__global__ void __launch_bounds__(256) gather_kernel(
        const int* __restrict__ seq,
        const float* __restrict__ emb,
        float* __restrict__ out) {
    const unsigned int warp = (blockIdx.x * blockDim.x + threadIdx.x) >> 5;
    const unsigned int lane = threadIdx.x & 31u;
    const unsigned int row0 = warp * ROWS_PER_WARP;

    // 16 indices in one coalesced LDG (lanes 0..15) — independent of norms
    int g = 0;
    if (lane < ROWS_PER_WARP) g = __ldg(seq + row0 + lane);

    const unsigned int m0 = row0 % M_GENES;    // may wrap the n boundary

    // Compute all 16 table-row ids first (pure ALU, no memory deps)
    unsigned int trow[ROWS_PER_WARP];
    #pragma unroll
    for (int r = 0; r < ROWS_PER_WARP; r++) {
        int gr = __shfl_sync(0xffffffffu, g, r);
        unsigned int m = m0 + r;
        if (m >= M_GENES) m -= M_GENES;
        trow[r] = m * N_NUC + gr;
    }

    // Issue 16 independent row loads back-to-back: true MLP=16
    float4 v[ROWS_PER_WARP];
    #pragma unroll
    for (int r = 0; r < ROWS_PER_WARP; r++)
        v[r] = __ldg(reinterpret_cast<const float4*>(
                         emb + (size_t)trow[r] * D_DIM) + lane);

#if __CUDA_ARCH__ >= 900
    cudaGridDependencySynchronize();       // wait for norms_kernel completion
#endif

    // 16 broadcast scalar inv-norm loads (L2-hit, independent)
    float s[ROWS_PER_WARP];
    #pragma unroll
    for (int r = 0; r < ROWS_PER_WARP; r++)
        s[r] = __ldg(g_inv_norm + trow[r]);

    // Scale + 16 streaming stores: 8 KB contiguous per warp
    float4* dst = reinterpret_cast<float4*>(out) + (size_t)row0 * 32 + lane;
    #pragma unroll
    for (int r = 0; r < ROWS_PER_WARP; r++) {
        float4 o;
        o.x = v[r].x * s[r];
        o.y = v[r].y * s[r];
        o.z = v[r].z * s[r];
        o.w = v[r].w * s[r];
        __stcs(dst + (size_t)r * 32, o);
    }
}

extern "C" void kernel_launch(void* const* d_in, const int* in_sizes, int n_in,
                              void* d_out, int out_size) {
    const int*   gene_seq = (const int*)d_in[0];     // (256, 2000) int32
    const float* emb      = (const float*)d_in[1];   // (2000, 4, 128) f32
    float*       out      = (float*)d_out;           // (256, 2000, 128) f32

    // Kernel 1: norms (1000 blocks, one wave)
    norms_kernel<<<(TABLE_ROWS * 32 + 255) / 256, 256>>>(emb);

    // Kernel 2: gather with PDL (prologue overlaps kernel 1's tail)
    cudaLaunchConfig_t cfg = {};
    cfg.gridDim  = dim3(TOTAL_ROWS / ROWS_PER_WARP / 8);   // 4000 blocks
    cfg.blockDim = dim3(256);
    cfg.dynamicSmemBytes = 0;
    cfg.stream = 0;

    cudaLaunchAttribute attr[1];
    attr[0].id = cudaLaunchAttributeProgrammaticStreamSerialization;
    attr[0].val.programmaticStreamSerializationAllowed = 1;
    cfg.attrs = attr;
    cfg.numAttrs = 1;

    cudaLaunchKernelEx(&cfg, gather_kernel, gene_seq, emb, (float*)d_out);
}

// round 13
// speedup vs baseline: 1.0007x; 1.0007x over previous
#include <cuda_runtime.h>
#include <cuda_bf16.h>

#define N_SEQ   256
#define M_GENES 2000
#define D_DIM   128
#define N_NUC   4
#define MT      16                    // genes per tile
#define NTT     16                    // sequences per tile
#define M_TILES (M_GENES / MT)        // 125
#define N_TILES (N_SEQ / NTT)         // 16
#define SEG_ROWS (MT * N_NUC)         // 64 table rows per tile

// Single fused kernel: tile = 16 sequences x 16 genes.
// Phase 1: load + normalize 64 table rows (32 KB) into smem.
// Phase 2: gather from smem, write 8 KB contiguous chunks per (warp, n).
// L2 read traffic: 64 MB (vs 262 MB flat); writes stay fully coalesced.
__global__ void __launch_bounds__(256) fused_tile_kernel(
        const int* __restrict__ seq,
        const float* __restrict__ emb,
        float* __restrict__ out) {
    __shared__ float s_tab[SEG_ROWS * D_DIM];   // 32 KB
    __shared__ int   s_idx[NTT * MT];           // 1 KB

    const unsigned int mt = blockIdx.x % M_TILES;   // adjacent blocks -> adjacent m
    const unsigned int nt = blockIdx.x / M_TILES;
    const unsigned int m0 = mt * MT;
    const unsigned int n0 = nt * NTT;
    const unsigned int tid  = threadIdx.x;
    const unsigned int warp = tid >> 5;
    const unsigned int lane = tid & 31u;

    // ---- Indices: 256 ints, one per thread ----
    {
        int n = tid / MT, m = tid % MT;
        s_idx[tid] = __ldg(seq + (size_t)(n0 + n) * M_GENES + m0 + m);
    }

    // ---- Table: 64 contiguous rows starting at m0*4. Warp w owns rows
    //      [w*8, w*8+8), processed in 2 batches of 4 (MLP=4 loads, then
    //      4 interleaved warp allreduces). ----
    #pragma unroll
    for (int b = 0; b < 2; b++) {
        float4 v[4];
        float  ss[4];
        #pragma unroll
        for (int j = 0; j < 4; j++) {
            int r = warp * 8 + b * 4 + j;
            v[j] = __ldg(reinterpret_cast<const float4*>(
                        emb + ((size_t)m0 * N_NUC + r) * D_DIM) + lane);
        }
        #pragma unroll
        for (int j = 0; j < 4; j++)
            ss[j] = v[j].x * v[j].x + v[j].y * v[j].y
                  + v[j].z * v[j].z + v[j].w * v[j].w;
        #pragma unroll
        for (int o = 16; o > 0; o >>= 1) {
            #pragma unroll
            for (int j = 0; j < 4; j++)
                ss[j] += __shfl_xor_sync(0xffffffffu, ss[j], o);
        }
        #pragma unroll
        for (int j = 0; j < 4; j++) {
            int r = warp * 8 + b * 4 + j;
            float inv = 1.0f / fmaxf(sqrtf(ss[j]), 1e-12f);
            v[j].x *= inv; v[j].y *= inv; v[j].z *= inv; v[j].w *= inv;
            reinterpret_cast<float4*>(s_tab + (size_t)r * D_DIM)[lane] = v[j];
        }
    }
    __syncthreads();

    // ---- Emit: warp w serves n-locals {w, w+8}; per n, 16 m-consecutive
    //      rows = 8 KB contiguous. Batches of 8: 8 LDS.128 then 8 STG.128. ----
    #pragma unroll
    for (int nn = warp; nn < NTT; nn += 8) {
        float4* dst = reinterpret_cast<float4*>(
            out + ((size_t)(n0 + nn) * M_GENES + m0) * D_DIM) + lane;
        const int* idx = s_idx + nn * MT;
        #pragma unroll
        for (int b = 0; b < 2; b++) {
            float4 v[8];
            #pragma unroll
            for (int j = 0; j < 8; j++) {
                int m = b * 8 + j;
                int g = idx[m];                       // uniform -> LDS broadcast
                v[j] = reinterpret_cast<const float4*>(
                           s_tab + ((size_t)(m * N_NUC + g)) * D_DIM)[lane];
            }
            #pragma unroll
            for (int j = 0; j < 8; j++)
                __stcs(dst + (size_t)(b * 8 + j) * 32, v[j]);
        }
    }
}

extern "C" void kernel_launch(void* const* d_in, const int* in_sizes, int n_in,
                              void* d_out, int out_size) {
    const int*   gene_seq = (const int*)d_in[0];     // (256, 2000) int32
    const float* emb      = (const float*)d_in[1];   // (2000, 4, 128) f32
    float*       out      = (float*)d_out;           // (256, 2000, 128) f32

    fused_tile_kernel<<<M_TILES * N_TILES, 256>>>(gene_seq, emb, out);
}

// round 14
// speedup vs baseline: 1.0414x; 1.0406x over previous
#include <cuda_runtime.h>
#include <cuda_bf16.h>

#define N_SEQ   256
#define M_GENES 2000
#define D_DIM   128
#define N_NUC   4
#define MT      8                     // genes per tile
#define NTT     32                    // sequences per tile
#define M_TILES (M_GENES / MT)        // 250
#define N_TILES (N_SEQ / NTT)         // 8
#define SEG_ROWS (MT * N_NUC)         // 32 table rows per tile

// Single fused kernel: tile = 32 sequences x 8 genes.
// Phase 1: load + normalize 32 table rows (16 KB) into smem (one batch).
// Phase 2: gather from smem, write 4 KB contiguous chunks per (warp, n).
__global__ void __launch_bounds__(256) fused_tile_kernel(
        const int* __restrict__ seq,
        const float* __restrict__ emb,
        float* __restrict__ out) {
    __shared__ float s_tab[SEG_ROWS * D_DIM];   // 16 KB
    __shared__ int   s_idx[NTT * MT];           // 1 KB

    const unsigned int mt = blockIdx.x % M_TILES;   // adjacent blocks -> adjacent m
    const unsigned int nt = blockIdx.x / M_TILES;
    const unsigned int m0 = mt * MT;
    const unsigned int n0 = nt * NTT;
    const unsigned int tid  = threadIdx.x;
    const unsigned int warp = tid >> 5;
    const unsigned int lane = tid & 31u;

    // ---- Indices: 256 ints, one per thread (tid = n_local*MT + m_local) ----
    {
        int n = tid / MT, m = tid % MT;
        s_idx[tid] = __ldg(seq + (size_t)(n0 + n) * M_GENES + m0 + m);
    }

    // ---- Table: 32 contiguous rows from m0*4. Warp w owns rows [w*4, w*4+4):
    //      one batch of MLP=4 loads, 4 interleaved warp allreduces. ----
    {
        float4 v[4];
        float  ss[4];
        #pragma unroll
        for (int j = 0; j < 4; j++) {
            int r = warp * 4 + j;
            v[j] = __ldg(reinterpret_cast<const float4*>(
                        emb + ((size_t)m0 * N_NUC + r) * D_DIM) + lane);
        }
        #pragma unroll
        for (int j = 0; j < 4; j++)
            ss[j] = v[j].x * v[j].x + v[j].y * v[j].y
                  + v[j].z * v[j].z + v[j].w * v[j].w;
        #pragma unroll
        for (int o = 16; o > 0; o >>= 1) {
            #pragma unroll
            for (int j = 0; j < 4; j++)
                ss[j] += __shfl_xor_sync(0xffffffffu, ss[j], o);
        }
        #pragma unroll
        for (int j = 0; j < 4; j++) {
            int r = warp * 4 + j;
            float inv = 1.0f / fmaxf(sqrtf(ss[j]), 1e-12f);
            v[j].x *= inv; v[j].y *= inv; v[j].z *= inv; v[j].w *= inv;
            reinterpret_cast<float4*>(s_tab + (size_t)r * D_DIM)[lane] = v[j];
        }
    }
    __syncthreads();

    // ---- Emit: warp w serves n-locals {w, w+8, w+16, w+24}; per n,
    //      8 m-consecutive rows = 4 KB contiguous (R2's proven pattern).
    //      Batch: 8 conflict-free LDS.128, then 8 streaming STG.128. ----
    #pragma unroll
    for (int nn = warp; nn < NTT; nn += 8) {
        float4* dst = reinterpret_cast<float4*>(
            out + ((size_t)(n0 + nn) * M_GENES + m0) * D_DIM) + lane;
        const int* idx = s_idx + nn * MT;
        float4 v[MT];
        #pragma unroll
        for (int m = 0; m < MT; m++) {
            int g = idx[m];                        // uniform -> LDS broadcast
            v[m] = reinterpret_cast<const float4*>(
                       s_tab + ((size_t)(m * N_NUC + g)) * D_DIM)[lane];
        }
        #pragma unroll
        for (int m = 0; m < MT; m++)
            __stcs(dst + (size_t)m * 32, v[m]);
    }
}

extern "C" void kernel_launch(void* const* d_in, const int* in_sizes, int n_in,
                              void* d_out, int out_size) {
    const int*   gene_seq = (const int*)d_in[0];     // (256, 2000) int32
    const float* emb      = (const float*)d_in[1];   // (2000, 4, 128) f32
    float*       out      = (float*)d_out;           // (256, 2000, 128) f32

    fused_tile_kernel<<<M_TILES * N_TILES, 256>>>(gene_seq, emb, out);
}